// round 5
// baseline (speedup 1.0000x reference)
#include <cuda_runtime.h>
#include <cuda_bf16.h>
#include <cuda_fp16.h>
#include <cstdint>

#define BB 128
#define TT 512
#define HH 512
#define D2 1024
#define NOUT 64
#define VN 16
#define DACT 10
#define NTP 8   // ctx t-slices

// device scratch (no allocations allowed)
__device__ __nv_bfloat16 g_h[(size_t)BB * TT * D2];  // 134 MB relu(out) [b][t][d]
__device__ float g_wp[(size_t)BB * 32 * TT];         // warp logit partials [b][row][t]
__device__ float g_attn[(size_t)BB * TT];            // softmax weights
__device__ float g_ctxp[NTP][(size_t)BB * D2];       // context partials (8 t-slices)

__device__ __forceinline__ float fex2(float x) {
    float y; asm("ex2.approx.f32 %0, %1;" : "=f"(y) : "f"(x)); return y;
}
__device__ __forceinline__ float ftanh_a(float x) {
    float y; asm("tanh.approx.f32 %0, %1;" : "=f"(y) : "f"(x)); return y;
}
__device__ __forceinline__ __half2 qtanh_h2(__half2 x) {
    unsigned xi = *reinterpret_cast<unsigned*>(&x);
    unsigned yi;
    asm("tanh.approx.f16x2 %0, %1;" : "=r"(yi) : "r"(xi));
    return *reinterpret_cast<__half2*>(&yi);
}

// ---------------- K1: fused gate-GEMM + fo_pool scan ----------------
// block = (b, unit); unit = dir*4 + quarter; 128 threads = h in [q*128, q*128+128)
// smem (32256 B): tzf float2[VN*128] | ts2 float2[TT] | to float[VN*128] | vv short[TT] | buf float[4*160]
extern __shared__ float s_raw[];

__global__ void __launch_bounds__(128, 7) scan_kernel(
    const float* __restrict__ x,   // (B,T,3)
    const float* __restrict__ emb, // (16,10)
    const float* __restrict__ Wf, const float* __restrict__ bfw,
    const float* __restrict__ Wb, const float* __restrict__ bbw,
    const float* __restrict__ Mu)  // (2H,1)
{
    const int b    = blockIdx.x;
    const int unit = blockIdx.y;
    const int dir  = unit >> 2;
    const int q    = unit & 3;
    const int tid  = threadIdx.x;
    const int h    = q * 128 + tid;

    float2* tzf = (float2*)s_raw;                    // VN*128 float2 (16384 B)
    float2* ts2 = tzf + VN * 128;                    // TT float2     (4096 B)
    float*  to  = (float*)(ts2 + TT);                // VN*128        (8192 B)
    short*  vv  = (short*)(to + VN * 128);           // TT            (1024 B)
    float*  buf = (float*)(vv + TT);                 // 4*160         (2560 B)

    const float* W    = dir ? Wb : Wf;
    const float* bias = dir ? bbw : bfw;

    // stage x row into smem
    for (int t = tid; t < TT; t += 128) {
        const float* xp = x + ((size_t)b * TT + t) * 3;
        ts2[t] = make_float2(xp[0], xp[1]);
        vv[t]  = (short)(((int)xp[2]) << 7);         // pre-scaled v*128
    }

    const int ch_z = h, ch_f = HH + h, ch_o = 2 * HH + h;
    const float wz0 = W[ch_z], wz1 = W[1536 + ch_z];
    const float wf0 = W[ch_f], wf1 = W[1536 + ch_f];
    const float wo0 = W[ch_o], wo1 = W[1536 + ch_o];

    // build tables one gate at a time (keeps live regs low)
    {
        float wk[DACT];
#pragma unroll
        for (int k = 0; k < DACT; k++) wk[k] = W[(2 + k) * 1536 + ch_z];
        const float bz = bias[ch_z];
        for (int v = 0; v < VN; v++) {
            float a = bz;
#pragma unroll
            for (int k = 0; k < DACT; k++) a = fmaf(emb[v * DACT + k], wk[k], a);
            ((float*)tzf)[(v * 128 + tid) * 2] = a;
        }
#pragma unroll
        for (int k = 0; k < DACT; k++) wk[k] = W[(2 + k) * 1536 + ch_f];
        const float bfv = bias[ch_f];
        for (int v = 0; v < VN; v++) {
            float a = bfv;
#pragma unroll
            for (int k = 0; k < DACT; k++) a = fmaf(emb[v * DACT + k], wk[k], a);
            ((float*)tzf)[(v * 128 + tid) * 2 + 1] = a;
        }
#pragma unroll
        for (int k = 0; k < DACT; k++) wk[k] = W[(2 + k) * 1536 + ch_o];
        const float bo = bias[ch_o];
        for (int v = 0; v < VN; v++) {
            float a = bo;
#pragma unroll
            for (int k = 0; k < DACT; k++) a = fmaf(emb[v * DACT + k], wk[k], a);
            to[v * 128 + tid] = a;
        }
    }
    const int d = dir * HH + h;
    const float mu = Mu[d];
    __syncthreads();

    const int lane = tid & 31;
    const int wid  = tid >> 5;
    float* bufw = buf + wid * 160;                   // 32 x 5 padded tile
    const int rstep = dir ? -D2 : D2;

    float c = 0.0f;
    __nv_bfloat16* hp = g_h + ((size_t)b * TT + (dir ? TT - 1 : 0)) * D2 + d;
    float* wp_out = g_wp + ((size_t)b * 32 + unit * 4 + wid) * TT;

    for (int ch = 0; ch < TT / 4; ch++) {
#pragma unroll
        for (int j = 0; j < 4; j++) {
            const int i = ch * 4 + j;
            const int t = dir ? (TT - 1 - i) : i;
            const float2 tt = ts2[t];
            const int off = ((int)vv[t]) + tid;
            const float2 zf = tzf[off];
            const float aob = to[off];
            float az = fmaf(tt.x, wz0, fmaf(tt.y, wz1, zf.x));
            float af = fmaf(tt.x, wf0, fmaf(tt.y, wf1, zf.y));
            float ao = fmaf(tt.x, wo0, fmaf(tt.y, wo1, aob));
            float z = ftanh_a(az);
            // two sigmoids via one f16x2 tanh: sig(x) = 0.5*tanh(0.5x)+0.5
            __half2 tpair = qtanh_h2(__floats2half2_rn(0.5f * af, 0.5f * ao));
            float f = fmaf(__low2float(tpair),  0.5f, 0.5f);
            float o = fmaf(__high2float(tpair), 0.5f, 0.5f);
            c = fmaf(f, c - z, z);                   // f*c + (1-f)*z
            float hr = fmaxf(o * c, 0.0f);
            *hp = __float2bfloat16(hr); hp += rstep;
            bufw[lane * 5 + j] = hr * mu;
        }
        __syncwarp();
        {
            const int tl = lane >> 3;                // t_local 0..3
            const int s  = lane & 7;
            float p = bufw[(s     ) * 5 + tl]
                    + bufw[(s +  8) * 5 + tl]
                    + bufw[(s + 16) * 5 + tl]
                    + bufw[(s + 24) * 5 + tl];
            p += __shfl_xor_sync(0xffffffffu, p, 4);
            p += __shfl_xor_sync(0xffffffffu, p, 2);
            p += __shfl_xor_sync(0xffffffffu, p, 1);
            if (s == 0) {
                const int i = ch * 4 + tl;
                wp_out[dir ? (TT - 1 - i) : i] = p;
            }
        }
        __syncwarp();
    }
}

// ---------------- K2: reduce warp partials -> softmax over T ----------------
__global__ void __launch_bounds__(512) softmax_kernel()
{
    __shared__ float red[16];
    const int b = blockIdx.x;
    const int t = threadIdx.x;
    const int lane = t & 31, wid = t >> 5;

    const float* wp = g_wp + (size_t)b * 32 * TT + t;
    float s = 0.0f;
#pragma unroll
    for (int uw = 0; uw < 32; uw++) s += wp[(size_t)uw * TT];

    float m = s;
#pragma unroll
    for (int o = 16; o; o >>= 1) m = fmaxf(m, __shfl_xor_sync(0xffffffffu, m, o));
    if (lane == 0) red[wid] = m;
    __syncthreads();
    if (wid == 0) {
        float v = (lane < 16) ? red[lane] : -1e30f;
#pragma unroll
        for (int o = 16; o; o >>= 1) v = fmaxf(v, __shfl_xor_sync(0xffffffffu, v, o));
        if (lane == 0) red[0] = v;
    }
    __syncthreads();
    m = red[0];
    __syncthreads();

    float e = fex2(1.4426950408889634f * (s - m));
    float su = e;
#pragma unroll
    for (int o = 16; o; o >>= 1) su += __shfl_xor_sync(0xffffffffu, su, o);
    if (lane == 0) red[wid] = su;
    __syncthreads();
    if (wid == 0) {
        float v = (lane < 16) ? red[lane] : 0.0f;
#pragma unroll
        for (int o = 16; o; o >>= 1) v += __shfl_xor_sync(0xffffffffu, v, o);
        if (lane == 0) red[0] = v;
    }
    __syncthreads();
    g_attn[(size_t)b * TT + t] = e / red[0];
}

// ---------------- K3: context partials, vectorized uint4 (8 bf16/thread) ----------------
// block = 128 threads, each owns 8 consecutive d; grid = (B, NTP t-slices of 64)
__global__ void __launch_bounds__(128) ctx_kernel()
{
    __shared__ float a_sm[64];
    const int b  = blockIdx.x;
    const int tp = blockIdx.y;
    const int tid = threadIdx.x;
    const int t0 = tp * 64;

    if (tid < 64) a_sm[tid] = g_attn[(size_t)b * TT + t0 + tid];
    __syncthreads();

    const int d0 = tid * 8;
    const uint4* hp = (const uint4*)(g_h + ((size_t)b * TT + t0) * D2 + d0);
    const int step = D2 / 8;   // uint4 elements per t row

    float acc[8];
#pragma unroll
    for (int j = 0; j < 8; j++) acc[j] = 0.0f;

#pragma unroll 4
    for (int t = 0; t < 64; t++) {
        const uint4 w = hp[(size_t)t * step];
        const float a = a_sm[t];
        acc[0] = fmaf(a, __uint_as_float(w.x << 16),          acc[0]);
        acc[1] = fmaf(a, __uint_as_float(w.x & 0xffff0000u),  acc[1]);
        acc[2] = fmaf(a, __uint_as_float(w.y << 16),          acc[2]);
        acc[3] = fmaf(a, __uint_as_float(w.y & 0xffff0000u),  acc[3]);
        acc[4] = fmaf(a, __uint_as_float(w.z << 16),          acc[4]);
        acc[5] = fmaf(a, __uint_as_float(w.z & 0xffff0000u),  acc[5]);
        acc[6] = fmaf(a, __uint_as_float(w.w << 16),          acc[6]);
        acc[7] = fmaf(a, __uint_as_float(w.w & 0xffff0000u),  acc[7]);
    }
    float4* outp = (float4*)(&g_ctxp[tp][(size_t)b * D2 + d0]);
    outp[0] = make_float4(acc[0], acc[1], acc[2], acc[3]);
    outp[1] = make_float4(acc[4], acc[5], acc[6], acc[7]);
}

// ---------------- K4: relu(sum partials) @ W_out^T + b_out ----------------
__global__ void __launch_bounds__(512) out_kernel(
    const float* __restrict__ W_out, const float* __restrict__ b_out,
    float* __restrict__ out)
{
    __shared__ float ctx_s[D2];
    const int b = blockIdx.x;
    const int tid = threadIdx.x;
    const int lane = tid & 31, wid = tid >> 5;

#pragma unroll
    for (int half = 0; half < 2; half++) {
        const int d = half * 512 + tid;
        float s0 = 0.f, s1 = 0.f;
#pragma unroll
        for (int p = 0; p < NTP; p += 2) {
            s0 += g_ctxp[p][(size_t)b * D2 + d];
            s1 += g_ctxp[p + 1][(size_t)b * D2 + d];
        }
        ctx_s[d] = fmaxf(s0 + s1, 0.0f);
    }
    __syncthreads();

#pragma unroll
    for (int r = 0; r < 4; r++) {
        const int o = wid * 4 + r;
        const float* wrow = W_out + (size_t)o * D2;
        float v = 0.0f;
#pragma unroll
        for (int k = 0; k < D2 / 32; k++)
            v = fmaf(ctx_s[lane + k * 32], wrow[lane + k * 32], v);
#pragma unroll
        for (int off = 16; off; off >>= 1) v += __shfl_xor_sync(0xffffffffu, v, off);
        if (lane == 0) out[(size_t)b * NOUT + o] = v + b_out[o];
    }
}

extern "C" void kernel_launch(void* const* d_in, const int* in_sizes, int n_in,
                              void* d_out, int out_size) {
    const float* x     = (const float*)d_in[0];
    const float* emb   = (const float*)d_in[1];
    const float* Wf    = (const float*)d_in[2];
    const float* bf    = (const float*)d_in[3];
    const float* Wb    = (const float*)d_in[4];
    const float* bb    = (const float*)d_in[5];
    const float* Mu    = (const float*)d_in[6];
    const float* W_out = (const float*)d_in[7];
    const float* b_out = (const float*)d_in[8];
    float* out = (float*)d_out;

    // smem: 16384 + 4096 + 8192 + 1024 + 2560 = 32256 B (< 48KB default)
    scan_kernel<<<dim3(BB, 8), 128, 32256>>>(x, emb, Wf, bf, Wb, bb, Mu);
    softmax_kernel<<<BB, 512>>>();
    ctx_kernel<<<dim3(BB, NTP), 128>>>();
    out_kernel<<<BB, 512>>>(W_out, b_out, out);
}

// round 6
// speedup vs baseline: 1.5610x; 1.5610x over previous
#include <cuda_runtime.h>
#include <cuda_bf16.h>
#include <cstdint>

#define BB 128
#define TT 512
#define HH 512
#define D2 1024
#define NOUT 64
#define VN 16
#define DACT 10
#define NTP 8   // ctx t-slices

// device scratch (no allocations allowed)
__device__ __nv_bfloat16 g_h[(size_t)BB * TT * D2];  // 134 MB relu(out) [b][t][d]
__device__ float g_wp[(size_t)BB * 32 * TT];         // warp logit partials [b][row][t]
__device__ float g_attn[(size_t)BB * TT];            // softmax weights
__device__ float g_ctxp[NTP][(size_t)BB * D2];       // context partials (8 t-slices)

__device__ __forceinline__ float fex2(float x) {
    float y; asm("ex2.approx.f32 %0, %1;" : "=f"(y) : "f"(x)); return y;
}
__device__ __forceinline__ float ftanh_a(float x) {
    float y; asm("tanh.approx.f32 %0, %1;" : "=f"(y) : "f"(x)); return y;
}
__device__ __forceinline__ float fsig_a(float x) {
    return fmaf(ftanh_a(0.5f * x), 0.5f, 0.5f);
}

// ---------------- K1: fused gate-GEMM + fo_pool scan ----------------
// block = (b, unit); unit = dir*4 + quarter; 128 threads = h in [q*128, q*128+128)
// smem (32256 B): tzf float2[VN*128] | ts2 float2[TT] | to float[VN*128] | vv short[TT] | buf float[4*160]
extern __shared__ float s_raw[];

__global__ void __launch_bounds__(128, 7) scan_kernel(
    const float* __restrict__ x,   // (B,T,3)
    const float* __restrict__ emb, // (16,10)
    const float* __restrict__ Wf, const float* __restrict__ bfw,
    const float* __restrict__ Wb, const float* __restrict__ bbw,
    const float* __restrict__ Mu)  // (2H,1)
{
    const int b    = blockIdx.x;
    const int unit = blockIdx.y;
    const int dir  = unit >> 2;
    const int q    = unit & 3;
    const int tid  = threadIdx.x;
    const int h    = q * 128 + tid;

    float2* tzf = (float2*)s_raw;                    // VN*128 float2 (16384 B)
    float2* ts2 = tzf + VN * 128;                    // TT float2     (4096 B)
    float*  to  = (float*)(ts2 + TT);                // VN*128        (8192 B)
    short*  vv  = (short*)(to + VN * 128);           // TT            (1024 B)
    float*  buf = (float*)(vv + TT);                 // 4*160         (2560 B)

    const float* W    = dir ? Wb : Wf;
    const float* bias = dir ? bbw : bfw;

    // stage x row into smem
    for (int t = tid; t < TT; t += 128) {
        const float* xp = x + ((size_t)b * TT + t) * 3;
        ts2[t] = make_float2(xp[0], xp[1]);
        vv[t]  = (short)(((int)xp[2]) << 7);         // pre-scaled v*128
    }

    const int ch_z = h, ch_f = HH + h, ch_o = 2 * HH + h;
    const float wz0 = W[ch_z], wz1 = W[1536 + ch_z];
    const float wf0 = W[ch_f], wf1 = W[1536 + ch_f];
    const float wo0 = W[ch_o], wo1 = W[1536 + ch_o];

    // build tables one gate at a time (keeps live regs low)
    {
        float wk[DACT];
#pragma unroll
        for (int k = 0; k < DACT; k++) wk[k] = W[(2 + k) * 1536 + ch_z];
        const float bz = bias[ch_z];
        for (int v = 0; v < VN; v++) {
            float a = bz;
#pragma unroll
            for (int k = 0; k < DACT; k++) a = fmaf(emb[v * DACT + k], wk[k], a);
            ((float*)tzf)[(v * 128 + tid) * 2] = a;
        }
#pragma unroll
        for (int k = 0; k < DACT; k++) wk[k] = W[(2 + k) * 1536 + ch_f];
        const float bfv = bias[ch_f];
        for (int v = 0; v < VN; v++) {
            float a = bfv;
#pragma unroll
            for (int k = 0; k < DACT; k++) a = fmaf(emb[v * DACT + k], wk[k], a);
            ((float*)tzf)[(v * 128 + tid) * 2 + 1] = a;
        }
#pragma unroll
        for (int k = 0; k < DACT; k++) wk[k] = W[(2 + k) * 1536 + ch_o];
        const float bo = bias[ch_o];
        for (int v = 0; v < VN; v++) {
            float a = bo;
#pragma unroll
            for (int k = 0; k < DACT; k++) a = fmaf(emb[v * DACT + k], wk[k], a);
            to[v * 128 + tid] = a;
        }
    }
    const int d = dir * HH + h;
    const float mu = Mu[d];
    __syncthreads();

    const int lane = tid & 31;
    const int wid  = tid >> 5;
    float* bufw = buf + wid * 160;                   // 32 x 5 padded tile
    const int rstep = dir ? -D2 : D2;

    float c = 0.0f;
    __nv_bfloat16* hp = g_h + ((size_t)b * TT + (dir ? TT - 1 : 0)) * D2 + d;
    float* wp_out = g_wp + ((size_t)b * 32 + unit * 4 + wid) * TT;

    for (int ch = 0; ch < TT / 4; ch++) {
#pragma unroll
        for (int j = 0; j < 4; j++) {
            const int i = ch * 4 + j;
            const int t = dir ? (TT - 1 - i) : i;
            const float2 tt = ts2[t];
            const int off = ((int)vv[t]) + tid;
            const float2 zf = tzf[off];
            const float aob = to[off];
            float az = fmaf(tt.x, wz0, fmaf(tt.y, wz1, zf.x));
            float af = fmaf(tt.x, wf0, fmaf(tt.y, wf1, zf.y));
            float ao = fmaf(tt.x, wo0, fmaf(tt.y, wo1, aob));
            float z = ftanh_a(az);
            float f = fsig_a(af);
            float o = fsig_a(ao);
            c = fmaf(f, c - z, z);                   // f*c + (1-f)*z
            float hr = fmaxf(o * c, 0.0f);
            *hp = __float2bfloat16(hr); hp += rstep;
            bufw[lane * 5 + j] = hr * mu;
        }
        __syncwarp();
        {
            const int tl = lane >> 3;                // t_local 0..3
            const int s  = lane & 7;
            float p = bufw[(s     ) * 5 + tl]
                    + bufw[(s +  8) * 5 + tl]
                    + bufw[(s + 16) * 5 + tl]
                    + bufw[(s + 24) * 5 + tl];
            p += __shfl_xor_sync(0xffffffffu, p, 4);
            p += __shfl_xor_sync(0xffffffffu, p, 2);
            p += __shfl_xor_sync(0xffffffffu, p, 1);
            if (s == 0) {
                const int i = ch * 4 + tl;
                wp_out[dir ? (TT - 1 - i) : i] = p;
            }
        }
        __syncwarp();
    }
}

// ---------------- K2: reduce warp partials -> softmax over T ----------------
__global__ void __launch_bounds__(512) softmax_kernel()
{
    __shared__ float red[16];
    const int b = blockIdx.x;
    const int t = threadIdx.x;
    const int lane = t & 31, wid = t >> 5;

    const float* wp = g_wp + (size_t)b * 32 * TT + t;
    float s = 0.0f;
#pragma unroll
    for (int uw = 0; uw < 32; uw++) s += wp[(size_t)uw * TT];

    float m = s;
#pragma unroll
    for (int o = 16; o; o >>= 1) m = fmaxf(m, __shfl_xor_sync(0xffffffffu, m, o));
    if (lane == 0) red[wid] = m;
    __syncthreads();
    if (wid == 0) {
        float v = (lane < 16) ? red[lane] : -1e30f;
#pragma unroll
        for (int o = 16; o; o >>= 1) v = fmaxf(v, __shfl_xor_sync(0xffffffffu, v, o));
        if (lane == 0) red[0] = v;
    }
    __syncthreads();
    m = red[0];
    __syncthreads();

    float e = fex2(1.4426950408889634f * (s - m));
    float su = e;
#pragma unroll
    for (int o = 16; o; o >>= 1) su += __shfl_xor_sync(0xffffffffu, su, o);
    if (lane == 0) red[wid] = su;
    __syncthreads();
    if (wid == 0) {
        float v = (lane < 16) ? red[lane] : 0.0f;
#pragma unroll
        for (int o = 16; o; o >>= 1) v += __shfl_xor_sync(0xffffffffu, v, o);
        if (lane == 0) red[0] = v;
    }
    __syncthreads();
    g_attn[(size_t)b * TT + t] = e / red[0];
}

// ---------------- K3: context partials, vectorized uint4 (8 bf16/thread) ----------------
// block = 128 threads, each owns 8 consecutive d; grid = (B, NTP t-slices of 64)
__global__ void __launch_bounds__(128) ctx_kernel()
{
    __shared__ float a_sm[64];
    const int b  = blockIdx.x;
    const int tp = blockIdx.y;
    const int tid = threadIdx.x;
    const int t0 = tp * 64;

    if (tid < 64) a_sm[tid] = g_attn[(size_t)b * TT + t0 + tid];
    __syncthreads();

    const int d0 = tid * 8;
    const uint4* hp = (const uint4*)(g_h + ((size_t)b * TT + t0) * D2 + d0);
    const int step = D2 / 8;   // uint4 elements per t row

    float acc[8];
#pragma unroll
    for (int j = 0; j < 8; j++) acc[j] = 0.0f;

#pragma unroll 4
    for (int t = 0; t < 64; t++) {
        const uint4 w = hp[(size_t)t * step];
        const float a = a_sm[t];
        acc[0] = fmaf(a, __uint_as_float(w.x << 16),          acc[0]);
        acc[1] = fmaf(a, __uint_as_float(w.x & 0xffff0000u),  acc[1]);
        acc[2] = fmaf(a, __uint_as_float(w.y << 16),          acc[2]);
        acc[3] = fmaf(a, __uint_as_float(w.y & 0xffff0000u),  acc[3]);
        acc[4] = fmaf(a, __uint_as_float(w.z << 16),          acc[4]);
        acc[5] = fmaf(a, __uint_as_float(w.z & 0xffff0000u),  acc[5]);
        acc[6] = fmaf(a, __uint_as_float(w.w << 16),          acc[6]);
        acc[7] = fmaf(a, __uint_as_float(w.w & 0xffff0000u),  acc[7]);
    }
    float4* outp = (float4*)(&g_ctxp[tp][(size_t)b * D2 + d0]);
    outp[0] = make_float4(acc[0], acc[1], acc[2], acc[3]);
    outp[1] = make_float4(acc[4], acc[5], acc[6], acc[7]);
}

// ---------------- K4: relu(sum partials) @ W_out^T + b_out ----------------
__global__ void __launch_bounds__(512) out_kernel(
    const float* __restrict__ W_out, const float* __restrict__ b_out,
    float* __restrict__ out)
{
    __shared__ float ctx_s[D2];
    const int b = blockIdx.x;
    const int tid = threadIdx.x;
    const int lane = tid & 31, wid = tid >> 5;

#pragma unroll
    for (int half = 0; half < 2; half++) {
        const int d = half * 512 + tid;
        float s0 = 0.f, s1 = 0.f;
#pragma unroll
        for (int p = 0; p < NTP; p += 2) {
            s0 += g_ctxp[p][(size_t)b * D2 + d];
            s1 += g_ctxp[p + 1][(size_t)b * D2 + d];
        }
        ctx_s[d] = fmaxf(s0 + s1, 0.0f);
    }
    __syncthreads();

#pragma unroll
    for (int r = 0; r < 4; r++) {
        const int o = wid * 4 + r;
        const float* wrow = W_out + (size_t)o * D2;
        float v = 0.0f;
#pragma unroll
        for (int k = 0; k < D2 / 32; k++)
            v = fmaf(ctx_s[lane + k * 32], wrow[lane + k * 32], v);
#pragma unroll
        for (int off = 16; off; off >>= 1) v += __shfl_xor_sync(0xffffffffu, v, off);
        if (lane == 0) out[(size_t)b * NOUT + o] = v + b_out[o];
    }
}

extern "C" void kernel_launch(void* const* d_in, const int* in_sizes, int n_in,
                              void* d_out, int out_size) {
    const float* x     = (const float*)d_in[0];
    const float* emb   = (const float*)d_in[1];
    const float* Wf    = (const float*)d_in[2];
    const float* bf    = (const float*)d_in[3];
    const float* Wb    = (const float*)d_in[4];
    const float* bb    = (const float*)d_in[5];
    const float* Mu    = (const float*)d_in[6];
    const float* W_out = (const float*)d_in[7];
    const float* b_out = (const float*)d_in[8];
    float* out = (float*)d_out;

    // smem: 16384 + 4096 + 8192 + 1024 + 2560 = 32256 B (< 48KB default)
    scan_kernel<<<dim3(BB, 8), 128, 32256>>>(x, emb, Wf, bf, Wb, bb, Mu);
    softmax_kernel<<<BB, 512>>>();
    ctx_kernel<<<dim3(BB, NTP), 128>>>();
    out_kernel<<<BB, 512>>>(W_out, b_out, out);
}